// round 13
// baseline (speedup 1.0000x reference)
#include <cuda_runtime.h>
#include <cuda_bf16.h>
#include <mma.h>

using namespace nvcuda;

#define T_TOK 32768
#define DIM   1024
#define DFF   256
#define NE    8
#define TOPK  2
#define BM    128
#define BN    64
#define BK    32
#define PADROWS (T_TOK*TOPK + NE*BM)   /* 66560 */
#define MAXTM   (PADROWS/BM)           /* 520   */

// ---------------- scratch (static device allocations only) ----------------
__device__ __nv_bfloat16 g_xb[(size_t)T_TOK * DIM];      // x in bf16 (64 MB)
__device__ int           g_tok_e[T_TOK * TOPK];
__device__ float         g_tok_s[T_TOK * TOPK];
__device__ int           g_counts[NE];
__device__ int           g_poff[NE + 1];
__device__ int           g_cursor[NE];
__device__ int           g_row_token[PADROWS];
__device__ float         g_row_score[PADROWS];
__device__ __nv_bfloat16 g_h[(size_t)PADROWS * DFF];     // SwiGLU output (bf16)

__device__ __forceinline__ float bf16r(float v) {
    return __bfloat162float(__float2bfloat16(v));
}

// ---------------- init: zero output + counts ----------------
__global__ void init_kernel(float* __restrict__ out) {
    size_t i = (size_t)blockIdx.x * blockDim.x + threadIdx.x;
    size_t n = (size_t)T_TOK * DIM;
    for (size_t j = i; j < n; j += (size_t)gridDim.x * blockDim.x) out[j] = 0.f;
    if (i < NE) g_counts[i] = 0;
}

// ---------------- router: literal f32 softmax top-2 (proven-equivalent) -----
__global__ __launch_bounds__(256) void router_kernel(const float* __restrict__ x,
                                                     const float* __restrict__ rw) {
    __shared__ float s_rw[NE * DIM];   // 32 KB
    int tid = threadIdx.x;
    for (int i = tid; i < NE * DIM; i += blockDim.x) s_rw[i] = rw[i];
    __syncthreads();

    int warp = tid >> 5, lane = tid & 31;
    int t = blockIdx.x * 8 + warp;

    float xv[32];
    const float* xp = x + (size_t)t * DIM;
#pragma unroll
    for (int i = 0; i < 32; i++) xv[i] = xp[i * 32 + lane];

    __nv_bfloat16* xbp = g_xb + (size_t)t * DIM;
#pragma unroll
    for (int i = 0; i < 32; i++) xbp[i * 32 + lane] = __float2bfloat16(xv[i]);

    float l[NE];
#pragma unroll
    for (int e = 0; e < NE; e++) {
        float acc = 0.f;
        const float* rp = s_rw + e * DIM;
#pragma unroll
        for (int i = 0; i < 32; i++) acc += xv[i] * rp[i * 32 + lane];
#pragma unroll
        for (int o = 16; o; o >>= 1) acc += __shfl_xor_sync(0xffffffffu, acc, o);
        l[e] = acc;
    }

    if (lane == 0) {
        float mx = l[0];
#pragma unroll
        for (int e = 1; e < NE; e++) mx = fmaxf(mx, l[e]);
        float p[NE]; float Z = 0.f;
#pragma unroll
        for (int e = 0; e < NE; e++) p[e] = expf(l[e] - mx);
#pragma unroll
        for (int e = 0; e < NE; e++) Z += p[e];
        float tsc[NE];
#pragma unroll
        for (int e = 0; e < NE; e++) tsc[e] = p[e] / Z;
        int b0 = 0;
#pragma unroll
        for (int e = 1; e < NE; e++) if (tsc[e] > tsc[b0]) b0 = e;
        int b1 = (b0 == 0) ? 1 : 0;
#pragma unroll
        for (int e = 0; e < NE; e++) if (e != b0 && tsc[e] > tsc[b1]) b1 = e;
        float sum2 = tsc[b0] + tsc[b1];
        g_tok_e[2 * t + 0] = b0;  g_tok_e[2 * t + 1] = b1;
        g_tok_s[2 * t + 0] = tsc[b0] / sum2;
        g_tok_s[2 * t + 1] = tsc[b1] / sum2;
        atomicAdd(&g_counts[b0], 1);
        atomicAdd(&g_counts[b1], 1);
    }
}

// ---------------- scan / fill / build ----------------
__global__ void scan_kernel() {
    int off = 0;
    for (int e = 0; e < NE; e++) {
        g_poff[e]   = off;
        g_cursor[e] = 0;
        off += (g_counts[e] + BM - 1) & ~(BM - 1);
    }
    g_poff[NE] = off;
}

__global__ void fill_kernel() {
    int i = blockIdx.x * blockDim.x + threadIdx.x;
    if (i < PADROWS) g_row_token[i] = -1;
}

__global__ void build_kernel() {
    int t = blockIdx.x * blockDim.x + threadIdx.x;
    if (t >= T_TOK) return;
#pragma unroll
    for (int k = 0; k < TOPK; k++) {
        int e = g_tok_e[2 * t + k];
        int pos = g_poff[e] + atomicAdd(&g_cursor[e], 1);
        g_row_token[pos] = t;
        g_row_score[pos] = g_tok_s[2 * t + k];
    }
}

// ---------------- gemm13: fused x@w1, x@w3 + SwiGLU -> g_h (bf16) ----------------
__global__ __launch_bounds__(256) void gemm13_kernel(const float* __restrict__ w1,
                                                     const float* __restrict__ w3) {
    __shared__ __align__(16) unsigned char smem[34816];
    __shared__ int s_tok[BM];
    __shared__ int s_poff[NE + 1];
    const int LDA = 40, LDB = 72, LDO = 68;
    __nv_bfloat16* sA  = (__nv_bfloat16*)smem;                     // 128 x 40
    __nv_bfloat16* sB1 = (__nv_bfloat16*)(smem + 10240);           // 32 x 72
    __nv_bfloat16* sB3 = (__nv_bfloat16*)(smem + 10240 + 4608);    // 32 x 72
    float* sOut = (float*)smem;                                    // 128 x 68 (epilogue reuse)

    int tid = threadIdx.x;
    if (tid <= NE) s_poff[tid] = g_poff[tid];
    __syncthreads();

    int m0 = blockIdx.x * BM;
    if (m0 >= s_poff[NE]) return;
    int e = 0;
    while (m0 >= s_poff[e + 1]) e++;
    int n0 = blockIdx.y * BN;

    if (tid < BM) s_tok[tid] = g_row_token[m0 + tid];
    __syncthreads();

    int warp = tid >> 5;
    int wm = warp >> 1, wn = warp & 1;

    wmma::fragment<wmma::accumulator, 16, 16, 16, float> acc1[2][2], acc3[2][2];
#pragma unroll
    for (int i = 0; i < 2; i++)
#pragma unroll
        for (int j = 0; j < 2; j++) { wmma::fill_fragment(acc1[i][j], 0.f); wmma::fill_fragment(acc3[i][j], 0.f); }

    const float* w1e = w1 + (size_t)e * DIM * DFF;
    const float* w3e = w3 + (size_t)e * DIM * DFF;

    for (int kt = 0; kt < DIM / BK; kt++) {
        int k0 = kt * BK;
        // A tile: 128x32 bf16 gathered via row tokens
#pragma unroll
        for (int it = 0; it < 4; it++) {
            int lin = it * 1024 + tid * 4;
            int r = lin >> 5, c = lin & 31;
            int tok = s_tok[r];
            uint2 v = make_uint2(0u, 0u);
            if (tok >= 0) v = *(const uint2*)(g_xb + (size_t)tok * DIM + k0 + c);
            *(uint2*)&sA[r * LDA + c] = v;
        }
        // B tiles: 32x64 fp32 -> bf16 for both w1 and w3
#pragma unroll
        for (int it = 0; it < 2; it++) {
            int lin = it * 1024 + tid * 4;
            int r = lin >> 6, c = lin & 63;
            float4 v1 = *(const float4*)(w1e + (size_t)(k0 + r) * DFF + n0 + c);
            __nv_bfloat162 lo = __floats2bfloat162_rn(v1.x, v1.y);
            __nv_bfloat162 hi = __floats2bfloat162_rn(v1.z, v1.w);
            *(uint2*)&sB1[r * LDB + c] = make_uint2(*(unsigned*)&lo, *(unsigned*)&hi);
            float4 v3 = *(const float4*)(w3e + (size_t)(k0 + r) * DFF + n0 + c);
            lo = __floats2bfloat162_rn(v3.x, v3.y);
            hi = __floats2bfloat162_rn(v3.z, v3.w);
            *(uint2*)&sB3[r * LDB + c] = make_uint2(*(unsigned*)&lo, *(unsigned*)&hi);
        }
        __syncthreads();
#pragma unroll
        for (int kk = 0; kk < BK; kk += 16) {
            wmma::fragment<wmma::matrix_a, 16, 16, 16, __nv_bfloat16, wmma::row_major> fa[2];
            wmma::fragment<wmma::matrix_b, 16, 16, 16, __nv_bfloat16, wmma::row_major> fb1[2], fb3[2];
#pragma unroll
            for (int i = 0; i < 2; i++)
                wmma::load_matrix_sync(fa[i], &sA[(wm * 32 + 16 * i) * LDA + kk], LDA);
#pragma unroll
            for (int j = 0; j < 2; j++) {
                wmma::load_matrix_sync(fb1[j], &sB1[kk * LDB + wn * 32 + 16 * j], LDB);
                wmma::load_matrix_sync(fb3[j], &sB3[kk * LDB + wn * 32 + 16 * j], LDB);
            }
#pragma unroll
            for (int i = 0; i < 2; i++)
#pragma unroll
                for (int j = 0; j < 2; j++) {
                    wmma::mma_sync(acc1[i][j], fa[i], fb1[j], acc1[i][j]);
                    wmma::mma_sync(acc3[i][j], fa[i], fb3[j], acc3[i][j]);
                }
        }
        __syncthreads();
    }

    // SwiGLU epilogue — EAGER-MODE per-op bf16 semantics with a DECOMPOSED
    // sigmoid (each primitive materializes a bf16 array):
    //   x1,x3 = bf16(dot)
    //   e   = bf16( exp_f32(-x1) )
    //   den = bf16( 1 + e )
    //   sg  = bf16( 1 / den )
    //   s1  = bf16( x1 * sg )        (silu output)
    //   h   = bf16( s1 * x3 )
#pragma unroll
    for (int i = 0; i < 2; i++)
#pragma unroll
        for (int j = 0; j < 2; j++) {
            wmma::fragment<wmma::accumulator, 16, 16, 16, float> hf;
#pragma unroll
            for (int q = 0; q < 8; q++) {
                float a1  = bf16r(acc1[i][j].x[q]);
                float a3  = bf16r(acc3[i][j].x[q]);
                float ex  = bf16r(expf(-a1));
                float den = bf16r(1.f + ex);
                float sg  = bf16r(1.f / den);
                float s1  = bf16r(a1 * sg);
                hf.x[q] = s1 * a3;   // rounded to bf16 on the g_h store below
            }
            wmma::store_matrix_sync(&sOut[(wm * 32 + 16 * i) * LDO + wn * 32 + 16 * j], hf,
                                    LDO, wmma::mem_row_major);
        }
    __syncthreads();
#pragma unroll
    for (int it = 0; it < 8; it++) {
        int lin = it * 1024 + tid * 4;
        int r = lin >> 6, c = lin & 63;
        float4 v = *(const float4*)&sOut[r * LDO + c];
        __nv_bfloat162 lo = __floats2bfloat162_rn(v.x, v.y);
        __nv_bfloat162 hi = __floats2bfloat162_rn(v.z, v.w);
        *(uint2*)&g_h[(size_t)(m0 + r) * DFF + n0 + c] = make_uint2(*(unsigned*)&lo, *(unsigned*)&hi);
    }
}

// ---------------- gemm2: h @ w2 -> weighted scatter-add into out ----------------
__global__ __launch_bounds__(256) void gemm2_kernel(const float* __restrict__ w2,
                                                    float* __restrict__ out) {
    __shared__ __align__(16) unsigned char smem[34816];
    __shared__ int   s_tok[BM];
    __shared__ float s_sc[BM];
    __shared__ int   s_poff[NE + 1];
    const int LDA = 40, LDB = 72, LDO = 68;
    __nv_bfloat16* sA = (__nv_bfloat16*)smem;             // 128 x 40
    __nv_bfloat16* sB = (__nv_bfloat16*)(smem + 10240);   // 32 x 72
    float* sOut = (float*)smem;

    int tid = threadIdx.x;
    if (tid <= NE) s_poff[tid] = g_poff[tid];
    __syncthreads();

    int m0 = blockIdx.x * BM;
    if (m0 >= s_poff[NE]) return;
    int e = 0;
    while (m0 >= s_poff[e + 1]) e++;
    int n0 = blockIdx.y * BN;

    if (tid < BM) { s_tok[tid] = g_row_token[m0 + tid]; s_sc[tid] = g_row_score[m0 + tid]; }
    __syncthreads();

    int warp = tid >> 5;
    int wm = warp >> 1, wn = warp & 1;

    wmma::fragment<wmma::accumulator, 16, 16, 16, float> acc[2][2];
#pragma unroll
    for (int i = 0; i < 2; i++)
#pragma unroll
        for (int j = 0; j < 2; j++) wmma::fill_fragment(acc[i][j], 0.f);

    const float* w2e = w2 + (size_t)e * DFF * DIM;

    for (int kt = 0; kt < DFF / BK; kt++) {
        int k0 = kt * BK;
#pragma unroll
        for (int it = 0; it < 4; it++) {
            int lin = it * 1024 + tid * 4;
            int r = lin >> 5, c = lin & 31;
            *(uint2*)&sA[r * LDA + c] = *(const uint2*)(g_h + (size_t)(m0 + r) * DFF + k0 + c);
        }
#pragma unroll
        for (int it = 0; it < 2; it++) {
            int lin = it * 1024 + tid * 4;
            int r = lin >> 6, c = lin & 63;
            float4 v = *(const float4*)(w2e + (size_t)(k0 + r) * DIM + n0 + c);
            __nv_bfloat162 lo = __floats2bfloat162_rn(v.x, v.y);
            __nv_bfloat162 hi = __floats2bfloat162_rn(v.z, v.w);
            *(uint2*)&sB[r * LDB + c] = make_uint2(*(unsigned*)&lo, *(unsigned*)&hi);
        }
        __syncthreads();
#pragma unroll
        for (int kk = 0; kk < BK; kk += 16) {
            wmma::fragment<wmma::matrix_a, 16, 16, 16, __nv_bfloat16, wmma::row_major> fa[2];
            wmma::fragment<wmma::matrix_b, 16, 16, 16, __nv_bfloat16, wmma::row_major> fb[2];
#pragma unroll
            for (int i = 0; i < 2; i++)
                wmma::load_matrix_sync(fa[i], &sA[(wm * 32 + 16 * i) * LDA + kk], LDA);
#pragma unroll
            for (int j = 0; j < 2; j++)
                wmma::load_matrix_sync(fb[j], &sB[kk * LDB + wn * 32 + 16 * j], LDB);
#pragma unroll
            for (int i = 0; i < 2; i++)
#pragma unroll
                for (int j = 0; j < 2; j++)
                    wmma::mma_sync(acc[i][j], fa[i], fb[j], acc[i][j]);
        }
        __syncthreads();
    }

#pragma unroll
    for (int i = 0; i < 2; i++)
#pragma unroll
        for (int j = 0; j < 2; j++)
            wmma::store_matrix_sync(&sOut[(wm * 32 + 16 * i) * LDO + wn * 32 + 16 * j],
                                    acc[i][j], LDO, wmma::mem_row_major);
    __syncthreads();

#pragma unroll
    for (int it = 0; it < 8; it++) {
        int lin = it * 1024 + tid * 4;
        int r = lin >> 6, c = lin & 63;
        int tok = s_tok[r];
        if (tok >= 0) {
            float sc = s_sc[r];
            float4 v = *(const float4*)&sOut[r * LDO + c];
            float* op = out + (size_t)tok * DIM + n0 + c;
            // expert_out is a bf16 dot output; score multiply + scatter-add in f32
            atomicAdd(op + 0, bf16r(v.x) * sc);
            atomicAdd(op + 1, bf16r(v.y) * sc);
            atomicAdd(op + 2, bf16r(v.z) * sc);
            atomicAdd(op + 3, bf16r(v.w) * sc);
        }
    }
}

// ---------------- launch ----------------
extern "C" void kernel_launch(void* const* d_in, const int* in_sizes, int n_in,
                              void* d_out, int out_size) {
    const float* x  = (const float*)d_in[0];
    const float* rw = (const float*)d_in[1];
    const float* w1 = (const float*)d_in[2];
    const float* w2 = (const float*)d_in[3];
    const float* w3 = (const float*)d_in[4];
    float* out = (float*)d_out;

    init_kernel<<<1024, 256>>>(out);
    router_kernel<<<T_TOK / 8, 256>>>(x, rw);
    scan_kernel<<<1, 1>>>();
    fill_kernel<<<(PADROWS + 255) / 256, 256>>>();
    build_kernel<<<(T_TOK + 255) / 256, 256>>>();
    gemm13_kernel<<<dim3(MAXTM, DFF / BN), 256>>>(w1, w3);
    gemm2_kernel<<<dim3(MAXTM, DIM / BN), 256>>>(w2, out);
}

// round 14
// speedup vs baseline: 1.2714x; 1.2714x over previous
#include <cuda_runtime.h>
#include <cuda_bf16.h>
#include <mma.h>

using namespace nvcuda;

#define T_TOK 32768
#define DIM   1024
#define DFF   256
#define NE    8
#define TOPK  2
#define BM    128
#define BN    64
#define BK    32
#define PADROWS (T_TOK*TOPK + NE*BM)   /* 66560 */
#define MAXTM   (PADROWS/BM)           /* 520   */

// ---------------- scratch (static device allocations only) ----------------
__device__ __nv_bfloat16 g_xb[(size_t)T_TOK * DIM];      // x in bf16 (64 MB)
__device__ __nv_bfloat16 g_w1b[(size_t)NE * DIM * DFF];  // 4 MB
__device__ __nv_bfloat16 g_w3b[(size_t)NE * DIM * DFF];  // 4 MB
__device__ __nv_bfloat16 g_w2b[(size_t)NE * DFF * DIM];  // 4 MB
__device__ int           g_tok_e[T_TOK * TOPK];
__device__ float         g_tok_s[T_TOK * TOPK];
__device__ int           g_counts[NE];
__device__ int           g_poff[NE + 1];
__device__ int           g_cursor[NE];
__device__ int           g_row_token[PADROWS];
__device__ float         g_row_score[PADROWS];
__device__ __nv_bfloat16 g_h[(size_t)PADROWS * DFF];     // SwiGLU output (bf16)

__device__ __forceinline__ float bf16r(float v) {
    return __bfloat162float(__float2bfloat16(v));
}

__device__ __forceinline__ void cp16(void* dst_smem, const void* src) {
    unsigned d = (unsigned)__cvta_generic_to_shared(dst_smem);
    asm volatile("cp.async.cg.shared.global [%0], [%1], 16;\n" :: "r"(d), "l"(src));
}
#define CP_COMMIT() asm volatile("cp.async.commit_group;\n")
#define CP_WAIT(n)  asm volatile("cp.async.wait_group %0;\n" :: "n"(n))

// ---------------- init: zero output + counts ----------------
__global__ void init_kernel(float* __restrict__ out) {
    size_t i = (size_t)blockIdx.x * blockDim.x + threadIdx.x;
    size_t n = (size_t)T_TOK * DIM;
    for (size_t j = i; j < n; j += (size_t)gridDim.x * blockDim.x) out[j] = 0.f;
    if (i < NE) g_counts[i] = 0;
}

// ---------------- weight pre-conversion to bf16 (one pass) ----------------
__global__ void convert_w_kernel(const float* __restrict__ w1,
                                 const float* __restrict__ w3,
                                 const float* __restrict__ w2) {
    int i4 = blockIdx.x * blockDim.x + threadIdx.x;
    const int N4 = NE * DIM * DFF / 4;
    if (i4 >= N4) return;
    int i = i4 * 4;
    {
        float4 v = *(const float4*)(w1 + i);
        __nv_bfloat162 lo = __floats2bfloat162_rn(v.x, v.y);
        __nv_bfloat162 hi = __floats2bfloat162_rn(v.z, v.w);
        *(uint2*)&g_w1b[i] = make_uint2(*(unsigned*)&lo, *(unsigned*)&hi);
    }
    {
        float4 v = *(const float4*)(w3 + i);
        __nv_bfloat162 lo = __floats2bfloat162_rn(v.x, v.y);
        __nv_bfloat162 hi = __floats2bfloat162_rn(v.z, v.w);
        *(uint2*)&g_w3b[i] = make_uint2(*(unsigned*)&lo, *(unsigned*)&hi);
    }
    {
        float4 v = *(const float4*)(w2 + i);
        __nv_bfloat162 lo = __floats2bfloat162_rn(v.x, v.y);
        __nv_bfloat162 hi = __floats2bfloat162_rn(v.z, v.w);
        *(uint2*)&g_w2b[i] = make_uint2(*(unsigned*)&lo, *(unsigned*)&hi);
    }
}

// ---------------- router: literal f32 softmax top-2 ----------------
__global__ __launch_bounds__(256) void router_kernel(const float* __restrict__ x,
                                                     const float* __restrict__ rw) {
    __shared__ float s_rw[NE * DIM];   // 32 KB
    int tid = threadIdx.x;
    for (int i = tid; i < NE * DIM; i += blockDim.x) s_rw[i] = rw[i];
    __syncthreads();

    int warp = tid >> 5, lane = tid & 31;
    int t = blockIdx.x * 8 + warp;

    float xv[32];
    const float* xp = x + (size_t)t * DIM;
#pragma unroll
    for (int i = 0; i < 32; i++) xv[i] = xp[i * 32 + lane];

    __nv_bfloat16* xbp = g_xb + (size_t)t * DIM;
#pragma unroll
    for (int i = 0; i < 32; i++) xbp[i * 32 + lane] = __float2bfloat16(xv[i]);

    float l[NE];
#pragma unroll
    for (int e = 0; e < NE; e++) {
        float acc = 0.f;
        const float* rp = s_rw + e * DIM;
#pragma unroll
        for (int i = 0; i < 32; i++) acc += xv[i] * rp[i * 32 + lane];
#pragma unroll
        for (int o = 16; o; o >>= 1) acc += __shfl_xor_sync(0xffffffffu, acc, o);
        l[e] = acc;
    }

    if (lane == 0) {
        float mx = l[0];
#pragma unroll
        for (int e = 1; e < NE; e++) mx = fmaxf(mx, l[e]);
        float p[NE]; float Z = 0.f;
#pragma unroll
        for (int e = 0; e < NE; e++) p[e] = expf(l[e] - mx);
#pragma unroll
        for (int e = 0; e < NE; e++) Z += p[e];
        float tsc[NE];
#pragma unroll
        for (int e = 0; e < NE; e++) tsc[e] = p[e] / Z;
        int b0 = 0;
#pragma unroll
        for (int e = 1; e < NE; e++) if (tsc[e] > tsc[b0]) b0 = e;
        int b1 = (b0 == 0) ? 1 : 0;
#pragma unroll
        for (int e = 0; e < NE; e++) if (e != b0 && tsc[e] > tsc[b1]) b1 = e;
        float sum2 = tsc[b0] + tsc[b1];
        g_tok_e[2 * t + 0] = b0;  g_tok_e[2 * t + 1] = b1;
        g_tok_s[2 * t + 0] = tsc[b0] / sum2;
        g_tok_s[2 * t + 1] = tsc[b1] / sum2;
        atomicAdd(&g_counts[b0], 1);
        atomicAdd(&g_counts[b1], 1);
    }
}

// ---------------- scan / fill / build ----------------
__global__ void scan_kernel() {
    int off = 0;
    for (int e = 0; e < NE; e++) {
        g_poff[e]   = off;
        g_cursor[e] = 0;
        off += (g_counts[e] + BM - 1) & ~(BM - 1);
    }
    g_poff[NE] = off;
}

__global__ void fill_kernel() {
    int i = blockIdx.x * blockDim.x + threadIdx.x;
    if (i < PADROWS) g_row_token[i] = -1;
}

__global__ void build_kernel() {
    int t = blockIdx.x * blockDim.x + threadIdx.x;
    if (t >= T_TOK) return;
#pragma unroll
    for (int k = 0; k < TOPK; k++) {
        int e = g_tok_e[2 * t + k];
        int pos = g_poff[e] + atomicAdd(&g_cursor[e], 1);
        g_row_token[pos] = t;
        g_row_score[pos] = g_tok_s[2 * t + k];
    }
}

#define LDA 40
#define LDB 72
#define LDO 68

// ---------------- gemm13: pipelined, bf16 weights -> SwiGLU -> g_h ----------
__global__ __launch_bounds__(256) void gemm13_kernel() {
    // double-buffered tiles:
    //  sA : 2 x 128x40 bf16 = 20480 B
    //  sB1: 2 x 32x72  bf16 =  9216 B
    //  sB3: 2 x 32x72  bf16 =  9216 B   total 38912 B; epilogue reuses as f32 128x68
    __shared__ __align__(16) unsigned char smem[38912];
    __shared__ int s_tok[BM];
    __shared__ int s_poff[NE + 1];
    __nv_bfloat16* sA  = (__nv_bfloat16*)smem;                 // [2][128*LDA]
    __nv_bfloat16* sB1 = (__nv_bfloat16*)(smem + 20480);       // [2][32*LDB]
    __nv_bfloat16* sB3 = (__nv_bfloat16*)(smem + 20480 + 9216);
    float* sOut = (float*)smem;

    int tid = threadIdx.x;
    if (tid <= NE) s_poff[tid] = g_poff[tid];
    __syncthreads();

    int m0 = blockIdx.x * BM;
    if (m0 >= s_poff[NE]) return;
    int e = 0;
    while (m0 >= s_poff[e + 1]) e++;
    int n0 = blockIdx.y * BN;

    if (tid < BM) s_tok[tid] = g_row_token[m0 + tid];
    __syncthreads();

    const __nv_bfloat16* w1e = g_w1b + (size_t)e * DIM * DFF;
    const __nv_bfloat16* w3e = g_w3b + (size_t)e * DIM * DFF;

    // per-stage loader: A gather (2 x 16B/thread) + B copies (1 x 16B/thread each)
    auto load_stage = [&](int st, int kt) {
        int k0 = kt * BK;
        __nv_bfloat16* A = sA + st * (BM * LDA);
#pragma unroll
        for (int i = 0; i < 2; i++) {
            int ch = tid * 2 + i;            // 512 chunks: 4 per row
            int r = ch >> 2, c8 = (ch & 3) * 8;
            int tok = s_tok[r];
            __nv_bfloat16* dst = &A[r * LDA + c8];
            if (tok >= 0) cp16(dst, g_xb + (size_t)tok * DIM + k0 + c8);
            else *(uint4*)dst = make_uint4(0u, 0u, 0u, 0u);
        }
        {
            int ch = tid;                    // 256 chunks: 8 per row (64 bf16)
            int r = ch >> 3, c8 = (ch & 7) * 8;
            cp16(&sB1[st * (BK * LDB) + r * LDB + c8], w1e + (size_t)(k0 + r) * DFF + n0 + c8);
            cp16(&sB3[st * (BK * LDB) + r * LDB + c8], w3e + (size_t)(k0 + r) * DFF + n0 + c8);
        }
    };

    int warp = tid >> 5;
    int wm = warp >> 1, wn = warp & 1;

    wmma::fragment<wmma::accumulator, 16, 16, 16, float> acc1[2][2], acc3[2][2];
#pragma unroll
    for (int i = 0; i < 2; i++)
#pragma unroll
        for (int j = 0; j < 2; j++) { wmma::fill_fragment(acc1[i][j], 0.f); wmma::fill_fragment(acc3[i][j], 0.f); }

    const int KT = DIM / BK;   // 32
    load_stage(0, 0);
    CP_COMMIT();

    for (int kt = 0; kt < KT; kt++) {
        int st = kt & 1;
        if (kt + 1 < KT) { load_stage(st ^ 1, kt + 1); CP_COMMIT(); CP_WAIT(1); }
        else             { CP_WAIT(0); }
        __syncthreads();

        __nv_bfloat16* A  = sA  + st * (BM * LDA);
        __nv_bfloat16* B1 = sB1 + st * (BK * LDB);
        __nv_bfloat16* B3 = sB3 + st * (BK * LDB);
#pragma unroll
        for (int kk = 0; kk < BK; kk += 16) {
            wmma::fragment<wmma::matrix_a, 16, 16, 16, __nv_bfloat16, wmma::row_major> fa[2];
            wmma::fragment<wmma::matrix_b, 16, 16, 16, __nv_bfloat16, wmma::row_major> fb1[2], fb3[2];
#pragma unroll
            for (int i = 0; i < 2; i++)
                wmma::load_matrix_sync(fa[i], &A[(wm * 32 + 16 * i) * LDA + kk], LDA);
#pragma unroll
            for (int j = 0; j < 2; j++) {
                wmma::load_matrix_sync(fb1[j], &B1[kk * LDB + wn * 32 + 16 * j], LDB);
                wmma::load_matrix_sync(fb3[j], &B3[kk * LDB + wn * 32 + 16 * j], LDB);
            }
#pragma unroll
            for (int i = 0; i < 2; i++)
#pragma unroll
                for (int j = 0; j < 2; j++) {
                    wmma::mma_sync(acc1[i][j], fa[i], fb1[j], acc1[i][j]);
                    wmma::mma_sync(acc3[i][j], fa[i], fb3[j], acc3[i][j]);
                }
        }
        __syncthreads();
    }

    // SwiGLU epilogue — EXACT eager-mode per-op bf16 chain (frozen):
    //   x1,x3 = bf16(dot); e=bf16(exp(-x1)); den=bf16(1+e); sg=bf16(1/den);
    //   s1=bf16(x1*sg); h=bf16(s1*x3)
#pragma unroll
    for (int i = 0; i < 2; i++)
#pragma unroll
        for (int j = 0; j < 2; j++) {
            wmma::fragment<wmma::accumulator, 16, 16, 16, float> hf;
#pragma unroll
            for (int q = 0; q < 8; q++) {
                float a1  = bf16r(acc1[i][j].x[q]);
                float a3  = bf16r(acc3[i][j].x[q]);
                float ex  = bf16r(expf(-a1));
                float den = bf16r(1.f + ex);
                float sg  = bf16r(1.f / den);
                float s1  = bf16r(a1 * sg);
                hf.x[q] = s1 * a3;
            }
            wmma::store_matrix_sync(&sOut[(wm * 32 + 16 * i) * LDO + wn * 32 + 16 * j], hf,
                                    LDO, wmma::mem_row_major);
        }
    __syncthreads();
#pragma unroll
    for (int it = 0; it < 8; it++) {
        int lin = it * 1024 + tid * 4;
        int r = lin >> 6, c = lin & 63;
        float4 v = *(const float4*)&sOut[r * LDO + c];
        __nv_bfloat162 lo = __floats2bfloat162_rn(v.x, v.y);
        __nv_bfloat162 hi = __floats2bfloat162_rn(v.z, v.w);
        *(uint2*)&g_h[(size_t)(m0 + r) * DFF + n0 + c] = make_uint2(*(unsigned*)&lo, *(unsigned*)&hi);
    }
}

// ---------------- gemm2: pipelined, bf16 w2 -> weighted scatter-add ----------
__global__ __launch_bounds__(256) void gemm2_kernel(float* __restrict__ out) {
    // sA: 2 x 128x40 = 20480 B, sB: 2 x 32x72 = 9216 B -> 29696; sOut f32 needs 34816
    __shared__ __align__(16) unsigned char smem[34816];
    __shared__ int   s_tok[BM];
    __shared__ float s_sc[BM];
    __shared__ int   s_poff[NE + 1];
    __nv_bfloat16* sA = (__nv_bfloat16*)smem;             // [2][128*LDA]
    __nv_bfloat16* sB = (__nv_bfloat16*)(smem + 20480);   // [2][32*LDB]
    float* sOut = (float*)smem;

    int tid = threadIdx.x;
    if (tid <= NE) s_poff[tid] = g_poff[tid];
    __syncthreads();

    int m0 = blockIdx.x * BM;
    if (m0 >= s_poff[NE]) return;
    int e = 0;
    while (m0 >= s_poff[e + 1]) e++;
    int n0 = blockIdx.y * BN;

    if (tid < BM) { s_tok[tid] = g_row_token[m0 + tid]; s_sc[tid] = g_row_score[m0 + tid]; }
    __syncthreads();

    const __nv_bfloat16* w2e = g_w2b + (size_t)e * DFF * DIM;

    auto load_stage = [&](int st, int kt) {
        int k0 = kt * BK;
        __nv_bfloat16* A = sA + st * (BM * LDA);
#pragma unroll
        for (int i = 0; i < 2; i++) {
            int ch = tid * 2 + i;
            int r = ch >> 2, c8 = (ch & 3) * 8;
            cp16(&A[r * LDA + c8], g_h + (size_t)(m0 + r) * DFF + k0 + c8);
        }
        {
            int ch = tid;
            int r = ch >> 3, c8 = (ch & 7) * 8;
            cp16(&sB[st * (BK * LDB) + r * LDB + c8], w2e + (size_t)(k0 + r) * DIM + n0 + c8);
        }
    };

    int warp = tid >> 5;
    int wm = warp >> 1, wn = warp & 1;

    wmma::fragment<wmma::accumulator, 16, 16, 16, float> acc[2][2];
#pragma unroll
    for (int i = 0; i < 2; i++)
#pragma unroll
        for (int j = 0; j < 2; j++) wmma::fill_fragment(acc[i][j], 0.f);

    const int KT = DFF / BK;   // 8
    load_stage(0, 0);
    CP_COMMIT();

    for (int kt = 0; kt < KT; kt++) {
        int st = kt & 1;
        if (kt + 1 < KT) { load_stage(st ^ 1, kt + 1); CP_COMMIT(); CP_WAIT(1); }
        else             { CP_WAIT(0); }
        __syncthreads();

        __nv_bfloat16* A = sA + st * (BM * LDA);
        __nv_bfloat16* B = sB + st * (BK * LDB);
#pragma unroll
        for (int kk = 0; kk < BK; kk += 16) {
            wmma::fragment<wmma::matrix_a, 16, 16, 16, __nv_bfloat16, wmma::row_major> fa[2];
            wmma::fragment<wmma::matrix_b, 16, 16, 16, __nv_bfloat16, wmma::row_major> fb[2];
#pragma unroll
            for (int i = 0; i < 2; i++)
                wmma::load_matrix_sync(fa[i], &A[(wm * 32 + 16 * i) * LDA + kk], LDA);
#pragma unroll
            for (int j = 0; j < 2; j++)
                wmma::load_matrix_sync(fb[j], &B[kk * LDB + wn * 32 + 16 * j], LDB);
#pragma unroll
            for (int i = 0; i < 2; i++)
#pragma unroll
                for (int j = 0; j < 2; j++)
                    wmma::mma_sync(acc[i][j], fa[i], fb[j], acc[i][j]);
        }
        __syncthreads();
    }

#pragma unroll
    for (int i = 0; i < 2; i++)
#pragma unroll
        for (int j = 0; j < 2; j++)
            wmma::store_matrix_sync(&sOut[(wm * 32 + 16 * i) * LDO + wn * 32 + 16 * j],
                                    acc[i][j], LDO, wmma::mem_row_major);
    __syncthreads();

#pragma unroll
    for (int it = 0; it < 8; it++) {
        int lin = it * 1024 + tid * 4;
        int r = lin >> 6, c = lin & 63;
        int tok = s_tok[r];
        if (tok >= 0) {
            float sc = s_sc[r];
            float4 v = *(const float4*)&sOut[r * LDO + c];
            float* op = out + (size_t)tok * DIM + n0 + c;
            atomicAdd(op + 0, bf16r(v.x) * sc);
            atomicAdd(op + 1, bf16r(v.y) * sc);
            atomicAdd(op + 2, bf16r(v.z) * sc);
            atomicAdd(op + 3, bf16r(v.w) * sc);
        }
    }
}

// ---------------- launch ----------------
extern "C" void kernel_launch(void* const* d_in, const int* in_sizes, int n_in,
                              void* d_out, int out_size) {
    const float* x  = (const float*)d_in[0];
    const float* rw = (const float*)d_in[1];
    const float* w1 = (const float*)d_in[2];
    const float* w2 = (const float*)d_in[3];
    const float* w3 = (const float*)d_in[4];
    float* out = (float*)d_out;

    init_kernel<<<1024, 256>>>(out);
    convert_w_kernel<<<(NE * DIM * DFF / 4 + 255) / 256, 256>>>(w1, w3, w2);
    router_kernel<<<T_TOK / 8, 256>>>(x, rw);
    scan_kernel<<<1, 1>>>();
    fill_kernel<<<(PADROWS + 255) / 256, 256>>>();
    build_kernel<<<(T_TOK + 255) / 256, 256>>>();
    gemm13_kernel<<<dim3(MAXTM, DFF / BN), 256>>>();
    gemm2_kernel<<<dim3(MAXTM, DIM / BN), 256>>>(out);
}